// round 7
// baseline (speedup 1.0000x reference)
#include <cuda_runtime.h>

#define BB 16
#define HH 512
#define WW 512
#define NPAIR (HH / 2)         // 256 two-row chunks per column

// exclusive column-prefix of dg_y at 2-row granularity: g_tab[b][pair][w]
__device__ float g_tab[(size_t)BB * NPAIR * WW];

__device__ __forceinline__ float dgf(float t) {
    return 2.0f / (1.0f + __expf(-t));   // c=2 logistic
}

// ---------------------------------------------------------------------------
// Kernel 1: 2-row-granularity exclusive column prefix of dg_y.
// Block: 512 thr = 32 w-lanes x 16 segs of 32 rows (16 pairs each).
// Grid: BB * (WW/32) = 256 blocks. Reads defgrad once, writes 8.4 MB table.
// ---------------------------------------------------------------------------
__global__ void __launch_bounds__(512) tab_kernel(const float2* __restrict__ dg2) {
    __shared__ float segsum[16][32];
    __shared__ float segoff[16][32];

    const int b   = blockIdx.x >> 4;
    const int w0  = (blockIdx.x & 15) * 32;
    const int wl  = threadIdx.x & 31;
    const int seg = threadIdx.x >> 5;          // 0..15, 32 rows each
    const int w   = w0 + wl;
    const int h0  = seg * 32;

    const float2* base = dg2 + ((size_t)b * HH + h0) * WW + w;

    float cs[16];                              // 16 pair sums (2 rows each)
    float tot = 0.f;
    #pragma unroll
    for (int c = 0; c < 16; c++) {
        float s = dgf(__ldg(&base[(size_t)(2 * c) * WW]).y)
                + dgf(__ldg(&base[(size_t)(2 * c + 1) * WW]).y);
        cs[c] = s;
        tot  += s;
    }
    segsum[seg][wl] = tot;
    __syncthreads();

    if (threadIdx.x < 32) {
        float a = 0.f;
        #pragma unroll
        for (int s2 = 0; s2 < 16; s2++) {
            float t = segsum[s2][threadIdx.x];
            segoff[s2][threadIdx.x] = a;       // exclusive seg prefix
            a += t;
        }
    }
    __syncthreads();

    float acc = segoff[seg][wl];
    float* t = g_tab + ((size_t)b * NPAIR + seg * 16) * WW + w;
    #pragma unroll
    for (int c = 0; c < 16; c++) {
        t[(size_t)c * WW] = acc;               // exclusive pair prefix
        acc += cs[c];
    }
}

// ---------------------------------------------------------------------------
// Kernel 2: TWO rows per block (R3 structure). Block scan of dg_x -> x_s,
// y_s from pair table + in-register dg_y, affine, grid3 smem-staged
// coalesced stores, 8 bilinear gathers in flight, out.
// Grid: BB*HH/2 = 4096 blocks of 512 threads.
// ---------------------------------------------------------------------------
__global__ void __launch_bounds__(512, 2) main_kernel(
    const float4* __restrict__ im4,
    const float2* __restrict__ defgrad2,
    const float*  __restrict__ affine,
    float4*       __restrict__ out4,
    float*        __restrict__ grid3)
{
    __shared__ float g3[2 * WW * 3];           // 12 KB grid3 staging
    __shared__ float wsum[2][16];

    const int b  = blockIdx.x >> 8;            // / NPAIR
    const int hp = blockIdx.x & (NPAIR - 1);
    const int h0 = hp * 2;
    const int w    = threadIdx.x;
    const int lane = w & 31;
    const int warp = w >> 5;

    const size_t row0 = ((size_t)b * HH + h0) * WW;   // row h0 base
    const size_t row1 = row0 + WW;

    // issue all independent loads up front
    const float2 dgA  = __ldg(defgrad2 + row0 + w);
    const float2 dgB  = __ldg(defgrad2 + row1 + w);
    const float  yoff = g_tab[((size_t)b * NPAIR + hp) * WW + w];

    const float* A = affine + b * 9;
    const float a0 = __ldg(A + 0) + 1.f, a1 = __ldg(A + 1),       a2 = __ldg(A + 2);
    const float a3 = __ldg(A + 3),       a4 = __ldg(A + 4) + 1.f, a5 = __ldg(A + 5);
    const float a6 = __ldg(A + 6),       a7 = __ldg(A + 7),       a8 = __ldg(A + 8) + 1.f;

    float v0 = dgf(dgA.x);
    float v1 = dgf(dgB.x);
    const float ys0 = yoff + dgf(dgA.y);
    const float ys1 = ys0  + dgf(dgB.y);

    // dual block-wide inclusive scan (both rows in parallel -> ILP)
    #pragma unroll
    for (int o = 1; o < 32; o <<= 1) {
        float n0 = __shfl_up_sync(0xffffffffu, v0, o);
        float n1 = __shfl_up_sync(0xffffffffu, v1, o);
        if (lane >= o) { v0 += n0; v1 += n1; }
    }
    if (lane == 31) { wsum[0][warp] = v0; wsum[1][warp] = v1; }
    __syncthreads();
    if (threadIdx.x < 32) {
        const int g = threadIdx.x >> 4, i = threadIdx.x & 15;
        float s = wsum[g][i];
        #pragma unroll
        for (int o = 1; o < 16; o <<= 1) {
            float n = __shfl_up_sync(0xffffffffu, s, o, 16);
            if (i >= o) s += n;
        }
        wsum[g][i] = s;
    }
    __syncthreads();
    const float xs0 = v0 + (warp ? wsum[0][warp - 1] : 0.f);
    const float xs1 = v1 + (warp ? wsum[1][warp - 1] : 0.f);

    // affine
    const float x_0 = a0 * xs0 + a1 * ys0 + a2;
    const float y_0 = a3 * xs0 + a4 * ys0 + a5;
    const float z_0 = a6 * xs0 + a7 * ys0 + a8;
    const float x_1 = a0 * xs1 + a1 * ys1 + a2;
    const float y_1 = a3 * xs1 + a4 * ys1 + a5;
    const float z_1 = a6 * xs1 + a7 * ys1 + a8;

    // corner indices
    const int fx0 = (int)floorf(x_0), fy0 = (int)floorf(y_0);
    const int fx1 = (int)floorf(x_1), fy1 = (int)floorf(y_1);
    const int x00 = min(max(fx0,     0), WW - 1);
    const int x01 = min(max(fx0 + 1, 0), WW - 1);
    const int y00 = min(max(fy0,     0), HH - 1);
    const int y01 = min(max(fy0 + 1, 0), HH - 1);
    const int x10 = min(max(fx1,     0), WW - 1);
    const int x11 = min(max(fx1 + 1, 0), WW - 1);
    const int y10 = min(max(fy1,     0), HH - 1);
    const int y11 = min(max(fy1 + 1, 0), HH - 1);

    // issue all 8 gathers before the grid3 staging barrier (overlap)
    const float4* imb = im4 + (size_t)b * HH * WW;
    const float4 Ia0 = __ldg(&imb[(size_t)y00 * WW + x00]);
    const float4 Ib0 = __ldg(&imb[(size_t)y01 * WW + x00]);
    const float4 Ic0 = __ldg(&imb[(size_t)y00 * WW + x01]);
    const float4 Id0 = __ldg(&imb[(size_t)y01 * WW + x01]);
    const float4 Ia1 = __ldg(&imb[(size_t)y10 * WW + x10]);
    const float4 Ib1 = __ldg(&imb[(size_t)y11 * WW + x10]);
    const float4 Ic1 = __ldg(&imb[(size_t)y10 * WW + x11]);
    const float4 Id1 = __ldg(&imb[(size_t)y11 * WW + x11]);

    // stage grid3 in smem, write back as coalesced float4s.
    // total = 2 rows * 512 * 3 floats = 3072 floats = 768 float4 = 512 + 256
    g3[w * 3 + 0]          = x_0;
    g3[w * 3 + 1]          = y_0;
    g3[w * 3 + 2]          = z_0;
    g3[WW * 3 + w * 3 + 0] = x_1;
    g3[WW * 3 + w * 3 + 1] = y_1;
    g3[WW * 3 + w * 3 + 2] = z_1;
    __syncthreads();
    {
        float4* dst = reinterpret_cast<float4*>(grid3 + row0 * 3);
        const float4* src = reinterpret_cast<const float4*>(g3);
        dst[threadIdx.x] = src[threadIdx.x];                      // 0..511
        if (threadIdx.x < 256)
            dst[threadIdx.x + 512] = src[threadIdx.x + 512];      // 512..767
    }

    // bilinear weights + combine (gathers have had the barrier to land)
    {
        const float wx1 = (float)x01 - x_0, wx0 = x_0 - (float)x00;
        const float wy1 = (float)y01 - y_0, wy0 = y_0 - (float)y00;
        const float wa = wx1 * wy1, wb = wx1 * wy0, wc = wx0 * wy1, wd = wx0 * wy0;
        float4 o;
        o.x = wa * Ia0.x + wb * Ib0.x + wc * Ic0.x + wd * Id0.x;
        o.y = wa * Ia0.y + wb * Ib0.y + wc * Ic0.y + wd * Id0.y;
        o.z = wa * Ia0.z + wb * Ib0.z + wc * Ic0.z + wd * Id0.z;
        o.w = wa * Ia0.w + wb * Ib0.w + wc * Ic0.w + wd * Id0.w;
        out4[row0 + w] = o;
    }
    {
        const float wx1 = (float)x11 - x_1, wx0 = x_1 - (float)x10;
        const float wy1 = (float)y11 - y_1, wy0 = y_1 - (float)y10;
        const float wa = wx1 * wy1, wb = wx1 * wy0, wc = wx0 * wy1, wd = wx0 * wy0;
        float4 o;
        o.x = wa * Ia1.x + wb * Ib1.x + wc * Ic1.x + wd * Id1.x;
        o.y = wa * Ia1.y + wb * Ib1.y + wc * Ic1.y + wd * Id1.y;
        o.z = wa * Ia1.z + wb * Ib1.z + wc * Ic1.z + wd * Id1.z;
        o.w = wa * Ia1.w + wb * Ib1.w + wc * Ic1.w + wd * Id1.w;
        out4[row1 + w] = o;
    }
}

// ---------------------------------------------------------------------------
extern "C" void kernel_launch(void* const* d_in, const int* in_sizes, int n_in,
                              void* d_out, int out_size) {
    const float4* im4      = (const float4*)d_in[0];   // [16,512,512,4] f32
    const float2* defgrad2 = (const float2*)d_in[1];   // [16,512,512,2] f32
    const float*  affine   = (const float*)d_in[2];    // [16,9] f32

    float* out   = (float*)d_out;
    float* grid3 = out + (size_t)in_sizes[0];          // out has im's element count

    tab_kernel<<<BB * (WW / 32), 512>>>(defgrad2);
    main_kernel<<<(unsigned)(BB * HH / 2), 512>>>(im4, defgrad2, affine,
                                                  (float4*)out, grid3);
}

// round 8
// speedup vs baseline: 1.1272x; 1.1272x over previous
#include <cuda_runtime.h>

#define BB 16
#define HH 512
#define WW 512
#define NPAIR (HH / 2)         // 256 two-row chunks per column

#define WT 16                  // w-lanes per tab block
#define NSEG 32                // segs per column
#define SROWS 16               // rows per seg (8 pairs)

// exclusive column-prefix of dg_y at 2-row granularity: g_tab[b][pair][w]
__device__ float g_tab[(size_t)BB * NPAIR * WW];

__device__ __forceinline__ float dgf(float t) {
    return 2.0f / (1.0f + __expf(-t));   // c=2 logistic
}

// ---------------------------------------------------------------------------
// Kernel 1: 2-row-granularity exclusive column prefix of dg_y.
// Block: 512 thr = 16 w-lanes x 32 segs of 16 rows (8 pairs each).
// Grid: BB * (WW/16) = 512 blocks (better wave balance on 148 SMs).
// ---------------------------------------------------------------------------
__global__ void __launch_bounds__(512) tab_kernel(const float2* __restrict__ dg2) {
    __shared__ float segsum[NSEG][WT];
    __shared__ float segoff[NSEG][WT];

    const int tilesPerB = WW / WT;             // 32
    const int b   = blockIdx.x / tilesPerB;
    const int w0  = (blockIdx.x % tilesPerB) * WT;
    const int wl  = threadIdx.x & (WT - 1);
    const int seg = threadIdx.x / WT;          // 0..31
    const int w   = w0 + wl;
    const int h0  = seg * SROWS;

    const float2* base = dg2 + ((size_t)b * HH + h0) * WW + w;

    float cs[8];                               // 8 pair sums (2 rows each)
    float tot = 0.f;
    #pragma unroll
    for (int c = 0; c < 8; c++) {
        float s = dgf(__ldg(&base[(size_t)(2 * c) * WW]).y)
                + dgf(__ldg(&base[(size_t)(2 * c + 1) * WW]).y);
        cs[c] = s;
        tot  += s;
    }
    segsum[seg][wl] = tot;
    __syncthreads();

    if (threadIdx.x < WT) {
        float a = 0.f;
        #pragma unroll
        for (int s2 = 0; s2 < NSEG; s2++) {
            float t = segsum[s2][threadIdx.x];
            segoff[s2][threadIdx.x] = a;       // exclusive seg prefix
            a += t;
        }
    }
    __syncthreads();

    float acc = segoff[seg][wl];
    float* t = g_tab + ((size_t)b * NPAIR + seg * 8) * WW + w;
    #pragma unroll
    for (int c = 0; c < 8; c++) {
        t[(size_t)c * WW] = acc;               // exclusive pair prefix
        acc += cs[c];
    }
}

// ---------------------------------------------------------------------------
// Kernel 2: grid only. 2 rows per block: block scan of dg_x -> x_s,
// y_s from pair table + in-register dg_y, affine, grid3 smem-staged
// coalesced float4 stores. Register-light -> full occupancy.
// Grid: BB*HH/2 = 4096 blocks of 512 threads.
// ---------------------------------------------------------------------------
__global__ void __launch_bounds__(512) grid_kernel(
    const float2* __restrict__ defgrad2,
    const float*  __restrict__ affine,
    float*        __restrict__ grid3)
{
    __shared__ float g3[2 * WW * 3];           // 12 KB staging
    __shared__ float wsum[2][16];

    const int b  = blockIdx.x >> 8;            // / NPAIR
    const int hp = blockIdx.x & (NPAIR - 1);
    const int h0 = hp * 2;
    const int w    = threadIdx.x;
    const int lane = w & 31;
    const int warp = w >> 5;

    const size_t row0 = ((size_t)b * HH + h0) * WW;
    const size_t row1 = row0 + WW;

    const float2 dgA  = __ldg(defgrad2 + row0 + w);
    const float2 dgB  = __ldg(defgrad2 + row1 + w);
    const float  yoff = g_tab[((size_t)b * NPAIR + hp) * WW + w];

    const float* A = affine + b * 9;
    const float a0 = __ldg(A + 0) + 1.f, a1 = __ldg(A + 1),       a2 = __ldg(A + 2);
    const float a3 = __ldg(A + 3),       a4 = __ldg(A + 4) + 1.f, a5 = __ldg(A + 5);
    const float a6 = __ldg(A + 6),       a7 = __ldg(A + 7),       a8 = __ldg(A + 8) + 1.f;

    float v0 = dgf(dgA.x);
    float v1 = dgf(dgB.x);
    const float ys0 = yoff + dgf(dgA.y);
    const float ys1 = ys0  + dgf(dgB.y);

    #pragma unroll
    for (int o = 1; o < 32; o <<= 1) {
        float n0 = __shfl_up_sync(0xffffffffu, v0, o);
        float n1 = __shfl_up_sync(0xffffffffu, v1, o);
        if (lane >= o) { v0 += n0; v1 += n1; }
    }
    if (lane == 31) { wsum[0][warp] = v0; wsum[1][warp] = v1; }
    __syncthreads();
    if (threadIdx.x < 32) {
        const int g = threadIdx.x >> 4, i = threadIdx.x & 15;
        float s = wsum[g][i];
        #pragma unroll
        for (int o = 1; o < 16; o <<= 1) {
            float n = __shfl_up_sync(0xffffffffu, s, o, 16);
            if (i >= o) s += n;
        }
        wsum[g][i] = s;
    }
    __syncthreads();
    const float xs0 = v0 + (warp ? wsum[0][warp - 1] : 0.f);
    const float xs1 = v1 + (warp ? wsum[1][warp - 1] : 0.f);

    g3[w * 3 + 0]          = a0 * xs0 + a1 * ys0 + a2;
    g3[w * 3 + 1]          = a3 * xs0 + a4 * ys0 + a5;
    g3[w * 3 + 2]          = a6 * xs0 + a7 * ys0 + a8;
    g3[WW * 3 + w * 3 + 0] = a0 * xs1 + a1 * ys1 + a2;
    g3[WW * 3 + w * 3 + 1] = a3 * xs1 + a4 * ys1 + a5;
    g3[WW * 3 + w * 3 + 2] = a6 * xs1 + a7 * ys1 + a8;
    __syncthreads();

    // 2 rows * 512 * 3 floats = 768 float4 = 512 + 256
    float4* dst = reinterpret_cast<float4*>(grid3 + row0 * 3);
    const float4* src = reinterpret_cast<const float4*>(g3);
    dst[threadIdx.x] = src[threadIdx.x];
    if (threadIdx.x < 256)
        dst[threadIdx.x + 512] = src[threadIdx.x + 512];
}

// ---------------------------------------------------------------------------
// Kernel 3: pure gather. 1 pixel/thread; reads x,y from grid3 (hot in L2),
// 4 scattered float4 gathers, bilinear combine, coalesced out store.
// Register-capped for >=6 blocks/SM -> 1536 thr/SM (75% occ) to hide the
// scattered-gather latency and saturate L1 wavefront throughput.
// Grid: BB*HH*WW/256 = 16384 blocks of 256 threads.
// ---------------------------------------------------------------------------
__global__ void __launch_bounds__(256, 6) gather_kernel(
    const float4* __restrict__ im4,
    const float*  __restrict__ grid3,
    float4*       __restrict__ out4)
{
    const int idx = blockIdx.x * 256 + threadIdx.x;    // global pixel id
    const int b   = idx >> 18;                          // / (512*512)

    const float x = __ldg(grid3 + (size_t)idx * 3);
    const float y = __ldg(grid3 + (size_t)idx * 3 + 1);

    const int fx = (int)floorf(x);
    const int fy = (int)floorf(y);
    const int x0 = min(max(fx,     0), WW - 1);
    const int x1 = min(max(fx + 1, 0), WW - 1);
    const int y0 = min(max(fy,     0), HH - 1);
    const int y1 = min(max(fy + 1, 0), HH - 1);

    const float4* imb = im4 + ((size_t)b << 18);
    const float4 Ia = __ldg(&imb[(size_t)y0 * WW + x0]);
    const float4 Ib = __ldg(&imb[(size_t)y1 * WW + x0]);
    const float4 Ic = __ldg(&imb[(size_t)y0 * WW + x1]);
    const float4 Id = __ldg(&imb[(size_t)y1 * WW + x1]);

    const float wx1 = (float)x1 - x, wx0 = x - (float)x0;
    const float wy1 = (float)y1 - y, wy0 = y - (float)y0;
    const float wa = wx1 * wy1, wb = wx1 * wy0, wc = wx0 * wy1, wd = wx0 * wy0;

    float4 o;
    o.x = wa * Ia.x + wb * Ib.x + wc * Ic.x + wd * Id.x;
    o.y = wa * Ia.y + wb * Ib.y + wc * Ic.y + wd * Id.y;
    o.z = wa * Ia.z + wb * Ib.z + wc * Ic.z + wd * Id.z;
    o.w = wa * Ia.w + wb * Ib.w + wc * Ic.w + wd * Id.w;
    out4[idx] = o;
}

// ---------------------------------------------------------------------------
extern "C" void kernel_launch(void* const* d_in, const int* in_sizes, int n_in,
                              void* d_out, int out_size) {
    const float4* im4      = (const float4*)d_in[0];   // [16,512,512,4] f32
    const float2* defgrad2 = (const float2*)d_in[1];   // [16,512,512,2] f32
    const float*  affine   = (const float*)d_in[2];    // [16,9] f32

    float* out   = (float*)d_out;
    float* grid3 = out + (size_t)in_sizes[0];          // out has im's element count

    tab_kernel<<<BB * (WW / WT), 512>>>(defgrad2);
    grid_kernel<<<(unsigned)(BB * HH / 2), 512>>>(defgrad2, affine, grid3);
    gather_kernel<<<(unsigned)(BB * HH * WW / 256), 256>>>(im4, grid3, (float4*)out);
}

// round 11
// speedup vs baseline: 1.1491x; 1.0194x over previous
#include <cuda_runtime.h>

#define BB 16
#define HH 512
#define WW 512
#define NPAIR (HH / 2)         // 256 two-row chunks per column

// exclusive column-prefix of dg_y at 2-row granularity: g_tab[b][pair][w]
__device__ float g_tab[(size_t)BB * NPAIR * WW];

__device__ __forceinline__ float dgf(float t) {
    return 2.0f / (1.0f + __expf(-t));   // c=2 logistic
}

// ---------------------------------------------------------------------------
// Kernel 1: 2-row-granularity exclusive column prefix of dg_y.
// Block: 256 thr = 8 float4-lanes (2 w each -> 16 w) x 32 segs of 16 rows.
// Full 128B lines per load instr; fine blocks for balance.
// Grid: BB * (WW/16) = 512 blocks.
// ---------------------------------------------------------------------------
__global__ void __launch_bounds__(256) tab_kernel(const float4* __restrict__ dg4) {
    __shared__ float segsum[32][16];
    __shared__ float segoff[32][16];

    const int b   = blockIdx.x >> 5;            // WW/16 = 32 tiles per batch
    const int w0  = (blockIdx.x & 31) * 16;
    const int ln  = threadIdx.x & 7;            // float4 lane: 2 columns
    const int seg = threadIdx.x >> 3;           // 0..31
    const int h0  = seg * 16;
    const int wA  = w0 + 2 * ln;                // even column
    const int f4c = wA >> 1;                    // float4 col within row (256/row)

    float csA[8], csB[8];
    float totA = 0.f, totB = 0.f;
    #pragma unroll
    for (int c = 0; c < 8; c++) {
        const float4 r0 = __ldg(&dg4[(size_t)(b * HH + h0 + 2 * c    ) * (WW / 2) + f4c]);
        const float4 r1 = __ldg(&dg4[(size_t)(b * HH + h0 + 2 * c + 1) * (WW / 2) + f4c]);
        const float sA = dgf(r0.y) + dgf(r1.y); // col wA:   (x,y) in .x,.y
        const float sB = dgf(r0.w) + dgf(r1.w); // col wA+1: (x,y) in .z,.w
        csA[c] = sA;  csB[c] = sB;
        totA += sA;   totB += sB;
    }
    segsum[seg][2 * ln]     = totA;
    segsum[seg][2 * ln + 1] = totB;
    __syncthreads();

    if (threadIdx.x < 16) {
        float a = 0.f;
        #pragma unroll
        for (int s2 = 0; s2 < 32; s2++) {
            float t = segsum[s2][threadIdx.x];
            segoff[s2][threadIdx.x] = a;        // exclusive seg prefix
            a += t;
        }
    }
    __syncthreads();

    float aA = segoff[seg][2 * ln];
    float aB = segoff[seg][2 * ln + 1];
    float2* t = reinterpret_cast<float2*>(g_tab + ((size_t)b * NPAIR + seg * 8) * WW + wA);
    #pragma unroll
    for (int c = 0; c < 8; c++) {
        t[(size_t)c * (WW / 2)] = make_float2(aA, aB);  // exclusive pair prefix
        aA += csA[c];
        aB += csB[c];
    }
}

// ---------------------------------------------------------------------------
// Kernel 2: grid only. 2 rows per block: block scan of dg_x -> x_s,
// y_s from pair table + in-register dg_y, affine, grid3 smem-staged
// coalesced float4 stores. Register-light -> full occupancy.
// Grid: BB*HH/2 = 4096 blocks of 512 threads.
// ---------------------------------------------------------------------------
__global__ void __launch_bounds__(512) grid_kernel(
    const float2* __restrict__ defgrad2,
    const float*  __restrict__ affine,
    float*        __restrict__ grid3)
{
    __shared__ float g3[2 * WW * 3];           // 12 KB staging
    __shared__ float wsum[2][16];

    const int b  = blockIdx.x >> 8;            // / NPAIR
    const int hp = blockIdx.x & (NPAIR - 1);
    const int h0 = hp * 2;
    const int w    = threadIdx.x;
    const int lane = w & 31;
    const int warp = w >> 5;

    const size_t row0 = ((size_t)b * HH + h0) * WW;
    const size_t row1 = row0 + WW;

    const float2 dgA  = __ldg(defgrad2 + row0 + w);
    const float2 dgB  = __ldg(defgrad2 + row1 + w);
    const float  yoff = g_tab[((size_t)b * NPAIR + hp) * WW + w];

    const float* A = affine + b * 9;
    const float a0 = __ldg(A + 0) + 1.f, a1 = __ldg(A + 1),       a2 = __ldg(A + 2);
    const float a3 = __ldg(A + 3),       a4 = __ldg(A + 4) + 1.f, a5 = __ldg(A + 5);
    const float a6 = __ldg(A + 6),       a7 = __ldg(A + 7),       a8 = __ldg(A + 8) + 1.f;

    float v0 = dgf(dgA.x);
    float v1 = dgf(dgB.x);
    const float ys0 = yoff + dgf(dgA.y);
    const float ys1 = ys0  + dgf(dgB.y);

    #pragma unroll
    for (int o = 1; o < 32; o <<= 1) {
        float n0 = __shfl_up_sync(0xffffffffu, v0, o);
        float n1 = __shfl_up_sync(0xffffffffu, v1, o);
        if (lane >= o) { v0 += n0; v1 += n1; }
    }
    if (lane == 31) { wsum[0][warp] = v0; wsum[1][warp] = v1; }
    __syncthreads();
    if (threadIdx.x < 32) {
        const int g = threadIdx.x >> 4, i = threadIdx.x & 15;
        float s = wsum[g][i];
        #pragma unroll
        for (int o = 1; o < 16; o <<= 1) {
            float n = __shfl_up_sync(0xffffffffu, s, o, 16);
            if (i >= o) s += n;
        }
        wsum[g][i] = s;
    }
    __syncthreads();
    const float xs0 = v0 + (warp ? wsum[0][warp - 1] : 0.f);
    const float xs1 = v1 + (warp ? wsum[1][warp - 1] : 0.f);

    g3[w * 3 + 0]          = a0 * xs0 + a1 * ys0 + a2;
    g3[w * 3 + 1]          = a3 * xs0 + a4 * ys0 + a5;
    g3[w * 3 + 2]          = a6 * xs0 + a7 * ys0 + a8;
    g3[WW * 3 + w * 3 + 0] = a0 * xs1 + a1 * ys1 + a2;
    g3[WW * 3 + w * 3 + 1] = a3 * xs1 + a4 * ys1 + a5;
    g3[WW * 3 + w * 3 + 2] = a6 * xs1 + a7 * ys1 + a8;
    __syncthreads();

    // 2 rows * 512 * 3 floats = 768 float4 = 512 + 256
    float4* dst = reinterpret_cast<float4*>(grid3 + row0 * 3);
    const float4* src = reinterpret_cast<const float4*>(g3);
    dst[threadIdx.x] = src[threadIdx.x];
    if (threadIdx.x < 256)
        dst[threadIdx.x + 512] = src[threadIdx.x + 512];
}

// ---------------------------------------------------------------------------
// Kernel 3: gather with VERTICAL PAIRING. Each thread does pixels (h,w) and
// (h+1,w). Along h, y advances by ~a4*dg (~1), so pixel1's corners usually
// coincide with pixel0's -> reuse registers (identical clamped index ==
// identical address => bit-exact), else load. Flattened selector logic.
// Grid: BB*(HH/2)*WW / 256 = 8192 blocks of 256 threads.
// ---------------------------------------------------------------------------
__global__ void __launch_bounds__(256, 5) gather_kernel(
    const float4* __restrict__ im4,
    const float*  __restrict__ grid3,
    float4*       __restrict__ out4)
{
    const int p   = blockIdx.x * 256 + threadIdx.x;  // pair id
    const int b   = p >> 17;                         // / (256*512)
    const int rem = p & 131071;
    const int hp  = rem >> 9;
    const int w   = rem & 511;

    const size_t idx0 = ((size_t)(b * HH + 2 * hp)) * WW + w;
    const size_t idx1 = idx0 + WW;

    const float x_0 = __ldg(grid3 + idx0 * 3);
    const float y_0 = __ldg(grid3 + idx0 * 3 + 1);
    const float x_1 = __ldg(grid3 + idx1 * 3);
    const float y_1 = __ldg(grid3 + idx1 * 3 + 1);

    const float4* imb = im4 + ((size_t)b << 18);

    // ---- pixel 0 ----
    const int fx0 = (int)floorf(x_0), fy0 = (int)floorf(y_0);
    const int X0 = min(max(fx0,     0), WW - 1);
    const int X1 = min(max(fx0 + 1, 0), WW - 1);
    const int Y0 = min(max(fy0,     0), HH - 1);
    const int Y1 = min(max(fy0 + 1, 0), HH - 1);

    const float4 Ia = __ldg(&imb[(size_t)Y0 * WW + X0]);
    const float4 Ib = __ldg(&imb[(size_t)Y1 * WW + X0]);
    const float4 Ic = __ldg(&imb[(size_t)Y0 * WW + X1]);
    const float4 Id = __ldg(&imb[(size_t)Y1 * WW + X1]);

    {
        const float wx1 = (float)X1 - x_0, wx0 = x_0 - (float)X0;
        const float wy1 = (float)Y1 - y_0, wy0 = y_0 - (float)Y0;
        const float wa = wx1 * wy1, wb = wx1 * wy0, wc = wx0 * wy1, wd = wx0 * wy0;
        float4 o;
        o.x = wa * Ia.x + wb * Ib.x + wc * Ic.x + wd * Id.x;
        o.y = wa * Ia.y + wb * Ib.y + wc * Ic.y + wd * Id.y;
        o.z = wa * Ia.z + wb * Ib.z + wc * Ic.z + wd * Id.z;
        o.w = wa * Ia.w + wb * Ib.w + wc * Ic.w + wd * Id.w;
        out4[idx0] = o;
    }

    // ---- pixel 1: reuse corner registers when clamped indices coincide ----
    const int fx1 = (int)floorf(x_1), fy1 = (int)floorf(y_1);
    const int U0 = min(max(fx1,     0), WW - 1);
    const int U1 = min(max(fx1 + 1, 0), WW - 1);
    const int V0 = min(max(fy1,     0), HH - 1);
    const int V1 = min(max(fy1 + 1, 0), HH - 1);

    const bool xs = (U0 == X0) && (U1 == X1);
    const bool r0top = xs && (V0 == Y0);   // V0 row matches pixel0 top
    const bool r0bot = xs && (V0 == Y1);   // V0 row matches pixel0 bottom
    const bool r1top = xs && (V1 == Y0);
    const bool r1bot = xs && (V1 == Y1);

    float4 Ja, Jb, Jc, Jd;
    if (r0bot)      { Ja = Ib; Jc = Id; }
    else if (r0top) { Ja = Ia; Jc = Ic; }
    else {
        Ja = __ldg(&imb[(size_t)V0 * WW + U0]);
        Jc = __ldg(&imb[(size_t)V0 * WW + U1]);
    }
    if (r1bot)      { Jb = Ib; Jd = Id; }
    else if (r1top) { Jb = Ia; Jd = Ic; }
    else {
        Jb = __ldg(&imb[(size_t)V1 * WW + U0]);
        Jd = __ldg(&imb[(size_t)V1 * WW + U1]);
    }

    {
        const float wx1 = (float)U1 - x_1, wx0 = x_1 - (float)U0;
        const float wy1 = (float)V1 - y_1, wy0 = y_1 - (float)V0;
        const float wa = wx1 * wy1, wb = wx1 * wy0, wc = wx0 * wy1, wd = wx0 * wy0;
        float4 o;
        o.x = wa * Ja.x + wb * Jb.x + wc * Jc.x + wd * Jd.x;
        o.y = wa * Ja.y + wb * Jb.y + wc * Jc.y + wd * Jd.y;
        o.z = wa * Ja.z + wb * Jb.z + wc * Jc.z + wd * Jd.z;
        o.w = wa * Ja.w + wb * Jb.w + wc * Jc.w + wd * Jd.w;
        out4[idx1] = o;
    }
}

// ---------------------------------------------------------------------------
extern "C" void kernel_launch(void* const* d_in, const int* in_sizes, int n_in,
                              void* d_out, int out_size) {
    const float4* im4      = (const float4*)d_in[0];   // [16,512,512,4] f32
    const float2* defgrad2 = (const float2*)d_in[1];   // [16,512,512,2] f32
    const float*  affine   = (const float*)d_in[2];    // [16,9] f32

    float* out   = (float*)d_out;
    float* grid3 = out + (size_t)in_sizes[0];          // out has im's element count

    tab_kernel<<<BB * (WW / 16), 256>>>((const float4*)defgrad2);
    grid_kernel<<<(unsigned)(BB * HH / 2), 512>>>(defgrad2, affine, grid3);
    gather_kernel<<<(unsigned)(BB * NPAIR * WW / 256), 256>>>(im4, grid3, (float4*)out);
}

// round 13
// speedup vs baseline: 1.1554x; 1.0055x over previous
#include <cuda_runtime.h>

#define BB 16
#define HH 512
#define WW 512
#define NPAIR (HH / 2)         // 256 two-row chunks per column

// exclusive column-prefix of dg_y at 2-row granularity: g_tab[b][pair][w]
__device__ float g_tab[(size_t)BB * NPAIR * WW];

__device__ __forceinline__ float dgf(float t) {
    return 2.0f / (1.0f + __expf(-t));   // c=2 logistic
}

// ---------------------------------------------------------------------------
// Kernel 1: 2-row-granularity exclusive column prefix of dg_y.
// Block: 512 thr = 8 float4-lanes (16 w) x 64 segs of 8 rows (4 pairs).
// Full 128B lines per row; 512 blocks x 512 thr = 262K threads (86% occ cap).
// Grid: BB * (WW/16) = 512 blocks.
// ---------------------------------------------------------------------------
__global__ void __launch_bounds__(512) tab_kernel(const float4* __restrict__ dg4) {
    __shared__ float segsum[64][16];
    __shared__ float segoff[64][16];

    const int b   = blockIdx.x >> 5;            // WW/16 = 32 tiles per batch
    const int w0  = (blockIdx.x & 31) * 16;
    const int ln  = threadIdx.x & 7;            // float4 lane: 2 columns
    const int seg = threadIdx.x >> 3;           // 0..63, 8 rows each
    const int h0  = seg * 8;
    const int wA  = w0 + 2 * ln;                // even column
    const int f4c = wA >> 1;                    // float4 col within row (256/row)

    float csA[4], csB[4];
    float totA = 0.f, totB = 0.f;
    #pragma unroll
    for (int c = 0; c < 4; c++) {
        const float4 r0 = __ldg(&dg4[(size_t)(b * HH + h0 + 2 * c    ) * (WW / 2) + f4c]);
        const float4 r1 = __ldg(&dg4[(size_t)(b * HH + h0 + 2 * c + 1) * (WW / 2) + f4c]);
        const float sA = dgf(r0.y) + dgf(r1.y); // col wA:   (x,y) in .x,.y
        const float sB = dgf(r0.w) + dgf(r1.w); // col wA+1: (x,y) in .z,.w
        csA[c] = sA;  csB[c] = sB;
        totA += sA;   totB += sB;
    }
    segsum[seg][2 * ln]     = totA;
    segsum[seg][2 * ln + 1] = totB;
    __syncthreads();

    if (threadIdx.x < 16) {
        float a = 0.f;
        #pragma unroll
        for (int s2 = 0; s2 < 64; s2++) {
            float t = segsum[s2][threadIdx.x];
            segoff[s2][threadIdx.x] = a;        // exclusive seg prefix
            a += t;
        }
    }
    __syncthreads();

    float aA = segoff[seg][2 * ln];
    float aB = segoff[seg][2 * ln + 1];
    float2* t = reinterpret_cast<float2*>(g_tab + ((size_t)b * NPAIR + seg * 4) * WW + wA);
    #pragma unroll
    for (int c = 0; c < 4; c++) {
        t[(size_t)c * (WW / 2)] = make_float2(aA, aB);  // exclusive pair prefix
        aA += csA[c];
        aB += csB[c];
    }
}

// ---------------------------------------------------------------------------
// Kernel 2: grid only. 2 rows per block: block scan of dg_x -> x_s,
// y_s from pair table + in-register dg_y, affine, grid3 smem-staged
// coalesced float4 stores. Register-light -> full occupancy.
// Grid: BB*HH/2 = 4096 blocks of 512 threads.
// ---------------------------------------------------------------------------
__global__ void __launch_bounds__(512) grid_kernel(
    const float2* __restrict__ defgrad2,
    const float*  __restrict__ affine,
    float*        __restrict__ grid3)
{
    __shared__ float g3[2 * WW * 3];           // 12 KB staging
    __shared__ float wsum[2][16];

    const int b  = blockIdx.x >> 8;            // / NPAIR
    const int hp = blockIdx.x & (NPAIR - 1);
    const int h0 = hp * 2;
    const int w    = threadIdx.x;
    const int lane = w & 31;
    const int warp = w >> 5;

    const size_t row0 = ((size_t)b * HH + h0) * WW;
    const size_t row1 = row0 + WW;

    const float2 dgA  = __ldg(defgrad2 + row0 + w);
    const float2 dgB  = __ldg(defgrad2 + row1 + w);
    const float  yoff = g_tab[((size_t)b * NPAIR + hp) * WW + w];

    const float* A = affine + b * 9;
    const float a0 = __ldg(A + 0) + 1.f, a1 = __ldg(A + 1),       a2 = __ldg(A + 2);
    const float a3 = __ldg(A + 3),       a4 = __ldg(A + 4) + 1.f, a5 = __ldg(A + 5);
    const float a6 = __ldg(A + 6),       a7 = __ldg(A + 7),       a8 = __ldg(A + 8) + 1.f;

    float v0 = dgf(dgA.x);
    float v1 = dgf(dgB.x);
    const float ys0 = yoff + dgf(dgA.y);
    const float ys1 = ys0  + dgf(dgB.y);

    #pragma unroll
    for (int o = 1; o < 32; o <<= 1) {
        float n0 = __shfl_up_sync(0xffffffffu, v0, o);
        float n1 = __shfl_up_sync(0xffffffffu, v1, o);
        if (lane >= o) { v0 += n0; v1 += n1; }
    }
    if (lane == 31) { wsum[0][warp] = v0; wsum[1][warp] = v1; }
    __syncthreads();
    if (threadIdx.x < 32) {
        const int g = threadIdx.x >> 4, i = threadIdx.x & 15;
        float s = wsum[g][i];
        #pragma unroll
        for (int o = 1; o < 16; o <<= 1) {
            float n = __shfl_up_sync(0xffffffffu, s, o, 16);
            if (i >= o) s += n;
        }
        wsum[g][i] = s;
    }
    __syncthreads();
    const float xs0 = v0 + (warp ? wsum[0][warp - 1] : 0.f);
    const float xs1 = v1 + (warp ? wsum[1][warp - 1] : 0.f);

    g3[w * 3 + 0]          = a0 * xs0 + a1 * ys0 + a2;
    g3[w * 3 + 1]          = a3 * xs0 + a4 * ys0 + a5;
    g3[w * 3 + 2]          = a6 * xs0 + a7 * ys0 + a8;
    g3[WW * 3 + w * 3 + 0] = a0 * xs1 + a1 * ys1 + a2;
    g3[WW * 3 + w * 3 + 1] = a3 * xs1 + a4 * ys1 + a5;
    g3[WW * 3 + w * 3 + 2] = a6 * xs1 + a7 * ys1 + a8;
    __syncthreads();

    // 2 rows * 512 * 3 floats = 768 float4 = 512 + 256
    float4* dst = reinterpret_cast<float4*>(grid3 + row0 * 3);
    const float4* src = reinterpret_cast<const float4*>(g3);
    dst[threadIdx.x] = src[threadIdx.x];
    if (threadIdx.x < 256)
        dst[threadIdx.x + 512] = src[threadIdx.x + 512];
}

// ---------------------------------------------------------------------------
// Kernel 3: gather, 2 vertically-adjacent pixels per thread, ALL 8 corner
// loads issued unconditionally up front (MLP=8, no branch serialization).
// Line reuse between the two pixels happens in L1 (same addresses hit).
// Grid: BB*(HH/2)*WW / 256 = 8192 blocks of 256 threads.
// ---------------------------------------------------------------------------
__global__ void __launch_bounds__(256, 5) gather_kernel(
    const float4* __restrict__ im4,
    const float*  __restrict__ grid3,
    float4*       __restrict__ out4)
{
    const int p   = blockIdx.x * 256 + threadIdx.x;  // pair id
    const int b   = p >> 17;                         // / (256*512)
    const int rem = p & 131071;
    const int hp  = rem >> 9;
    const int w   = rem & 511;

    const size_t idx0 = ((size_t)(b * HH + 2 * hp)) * WW + w;
    const size_t idx1 = idx0 + WW;

    const float x_0 = __ldg(grid3 + idx0 * 3);
    const float y_0 = __ldg(grid3 + idx0 * 3 + 1);
    const float x_1 = __ldg(grid3 + idx1 * 3);
    const float y_1 = __ldg(grid3 + idx1 * 3 + 1);

    const float4* imb = im4 + ((size_t)b << 18);

    const int fx0 = (int)floorf(x_0), fy0 = (int)floorf(y_0);
    const int fx1 = (int)floorf(x_1), fy1 = (int)floorf(y_1);
    const int X0 = min(max(fx0,     0), WW - 1);
    const int X1 = min(max(fx0 + 1, 0), WW - 1);
    const int Y0 = min(max(fy0,     0), HH - 1);
    const int Y1 = min(max(fy0 + 1, 0), HH - 1);
    const int U0 = min(max(fx1,     0), WW - 1);
    const int U1 = min(max(fx1 + 1, 0), WW - 1);
    const int V0 = min(max(fy1,     0), HH - 1);
    const int V1 = min(max(fy1 + 1, 0), HH - 1);

    // 8 independent gathers in flight
    const float4 Ia = __ldg(&imb[(size_t)Y0 * WW + X0]);
    const float4 Ib = __ldg(&imb[(size_t)Y1 * WW + X0]);
    const float4 Ic = __ldg(&imb[(size_t)Y0 * WW + X1]);
    const float4 Id = __ldg(&imb[(size_t)Y1 * WW + X1]);
    const float4 Ja = __ldg(&imb[(size_t)V0 * WW + U0]);
    const float4 Jb = __ldg(&imb[(size_t)V1 * WW + U0]);
    const float4 Jc = __ldg(&imb[(size_t)V0 * WW + U1]);
    const float4 Jd = __ldg(&imb[(size_t)V1 * WW + U1]);

    {
        const float wx1 = (float)X1 - x_0, wx0 = x_0 - (float)X0;
        const float wy1 = (float)Y1 - y_0, wy0 = y_0 - (float)Y0;
        const float wa = wx1 * wy1, wb = wx1 * wy0, wc = wx0 * wy1, wd = wx0 * wy0;
        float4 o;
        o.x = wa * Ia.x + wb * Ib.x + wc * Ic.x + wd * Id.x;
        o.y = wa * Ia.y + wb * Ib.y + wc * Ic.y + wd * Id.y;
        o.z = wa * Ia.z + wb * Ib.z + wc * Ic.z + wd * Id.z;
        o.w = wa * Ia.w + wb * Ib.w + wc * Ic.w + wd * Id.w;
        out4[idx0] = o;
    }
    {
        const float wx1 = (float)U1 - x_1, wx0 = x_1 - (float)U0;
        const float wy1 = (float)V1 - y_1, wy0 = y_1 - (float)V0;
        const float wa = wx1 * wy1, wb = wx1 * wy0, wc = wx0 * wy1, wd = wx0 * wy0;
        float4 o;
        o.x = wa * Ja.x + wb * Jb.x + wc * Jc.x + wd * Jd.x;
        o.y = wa * Ja.y + wb * Jb.y + wc * Jc.y + wd * Jd.y;
        o.z = wa * Ja.z + wb * Jb.z + wc * Jc.z + wd * Jd.z;
        o.w = wa * Ja.w + wb * Jb.w + wc * Jc.w + wd * Jd.w;
        out4[idx1] = o;
    }
}

// ---------------------------------------------------------------------------
extern "C" void kernel_launch(void* const* d_in, const int* in_sizes, int n_in,
                              void* d_out, int out_size) {
    const float4* im4      = (const float4*)d_in[0];   // [16,512,512,4] f32
    const float2* defgrad2 = (const float2*)d_in[1];   // [16,512,512,2] f32
    const float*  affine   = (const float*)d_in[2];    // [16,9] f32

    float* out   = (float*)d_out;
    float* grid3 = out + (size_t)in_sizes[0];          // out has im's element count

    tab_kernel<<<BB * (WW / 16), 512>>>((const float4*)defgrad2);
    grid_kernel<<<(unsigned)(BB * HH / 2), 512>>>(defgrad2, affine, grid3);
    gather_kernel<<<(unsigned)(BB * NPAIR * WW / 256), 256>>>(im4, grid3, (float4*)out);
}